// round 15
// baseline (speedup 1.0000x reference)
#include <cuda_runtime.h>
#include <cuda_fp16.h>
#include <cstdint>

#define N_ROWS  16384
#define DDIM    512
#define K_CODES 8192

#define MT 112                 // rows per CTA (147 CTAs = one wave on 148 SMs)
#define NCTA 147
#define NTT 128                // codes per tile
#define NTILES 64              // K_CODES / NTT
#define CAP 32
#define MARGIN 6.0e-4f
#define RG_BLOCKS 2048         // rescore/gather blocks (8 warps = 8 rows each)

// ---- scratch (__device__ globals; no cudaMalloc allowed) --------------------
__device__ float  g_snorm[N_ROWS];
__device__ float  g_cnorm[K_CODES];
__device__ double g_lpart[RG_BLOCKS];
__device__ __half g_xh[(size_t)N_ROWS * DDIM];
__device__ __half g_ch[(size_t)K_CODES * DDIM];
__device__ int    g_ccount[N_ROWS];
__device__ int    g_cand[(size_t)N_ROWS * CAP];

// ---- dynamic smem ------------------------------------------------------------
#define AS_OFF 0               // 64 k8-blocks x 112 rows x 16B = 114688
#define BS_OFF 114688          // 2 bufs x (16 k8 x 128 codes x 16B) = 65536
#define CN_OFF 180224          // 8192 cnorm floats = 32768
#define SMEM_SZ 212992

static __device__ __forceinline__ uint32_t smem_u32(const void* p) {
    uint32_t a;
    asm("{ .reg .u64 t; cvta.to.shared.u64 t, %1; cvt.u32.u64 %0, t; }"
        : "=r"(a) : "l"(p));
    return a;
}
static __device__ __forceinline__ void cp16(uint32_t dst, const void* src) {
    asm volatile("cp.async.ca.shared.global [%0], [%1], 16;"
                 :: "r"(dst), "l"(src) : "memory");
}
static __device__ __forceinline__ void cp_commit() {
    asm volatile("cp.async.commit_group;" ::: "memory");
}
static __device__ __forceinline__ void cp_wait_all() {
    asm volatile("cp.async.wait_group 0;" ::: "memory");
}

// ---------------------------------------------------------------------------
// Kernel 1: fp16 convert + exact fp32 row norms; zero counters.
// One warp per row.
// ---------------------------------------------------------------------------
__global__ void convert_kernel(const float* __restrict__ x,
                               const float* __restrict__ cb) {
    int gtid = blockIdx.x * blockDim.x + threadIdx.x;
    if (gtid < N_ROWS) g_ccount[gtid] = 0;
    int warp = gtid >> 5;
    int lane = threadIdx.x & 31;
    if (warp >= N_ROWS + K_CODES) return;
    bool isx = warp < N_ROWS;
    int row = isx ? warp : warp - N_ROWS;
    const float4* base = (const float4*)((isx ? x : cb) + (size_t)row * DDIM);
    __half2* dst = (__half2*)((isx ? g_xh : g_ch) + (size_t)row * DDIM);

    float s = 0.f;
#pragma unroll
    for (int j = 0; j < 4; j++) {
        float4 v = base[lane + 32 * j];
        s += v.x * v.x + v.y * v.y + v.z * v.z + v.w * v.w;
        dst[(lane + 32 * j) * 2]     = __floats2half2_rn(v.x, v.y);
        dst[(lane + 32 * j) * 2 + 1] = __floats2half2_rn(v.z, v.w);
    }
#pragma unroll
    for (int o = 16; o; o >>= 1) s += __shfl_xor_sync(0xffffffff, s, o);
    if (lane == 0) {
        if (isx) g_snorm[row] = s;
        else     g_cnorm[row] = s;
    }
}

// ---------------------------------------------------------------------------
// Kernel 2: HFMA2 packed-fp16 filter GEMM (proven config). 147 CTAs x
// 112 rows, one wave. 256 threads, thread tile 7x8, A + cnorm resident in
// smem, B double-buffered cp.async. Register row-min + candidate collect.
// ---------------------------------------------------------------------------
__global__ void __launch_bounds__(256, 1)
vq_gemm_kernel() {
    extern __shared__ char smem[];
    const uint32_t sb = smem_u32(smem);
    const int tid = threadIdx.x;
    const int tx  = tid & 15;          // code lane: codes tx + 16*j
    const int ty  = tid >> 4;          // row group: rows ty*7 + i
    const int row0 = blockIdx.x * MT;

    // prologue: resident A (clamped) + all 8192 cnorm + B chunk 0, one group
    for (int c = tid; c < 64 * MT; c += 256) {
        int r = c % MT, k8 = c / MT;
        int gr = row0 + r; if (gr >= N_ROWS) gr = N_ROWS - 1;
        cp16(sb + AS_OFF + (k8 * MT + r) * 16,
             g_xh + ((size_t)gr * DDIM + k8 * 8));
    }
    for (int c = tid; c < 2048; c += 256)          // cnorm: 8192 floats
        cp16(sb + CN_OFF + c * 16, g_cnorm + c * 4);
    for (int c = tid; c < 2048; c += 256) {
        int code = c & 127, k8l = c >> 7;
        cp16(sb + BS_OFF + (k8l * 128 + code) * 16,
             g_ch + ((size_t)code * DDIM + k8l * 8));
    }
    cp_commit();

    float runmin[7];
#pragma unroll
    for (int i = 0; i < 7; i++) runmin[i] = 3.4e38f;

    __half2 acc[7][8];
    const float* cns = (const float*)(smem + CN_OFF);

    for (int t = 0; t < NTILES; t++) {
        for (int kc = 0; kc < 4; kc++) {
            const int s = t * 4 + kc;
            const int buf = s & 1;
            cp_wait_all();
            __syncthreads();
            if (s + 1 < NTILES * 4) {     // prefetch next chunk
                const int nt = (s + 1) >> 2, nkc = (s + 1) & 3;
                const int nb = buf ^ 1;
                for (int c = tid; c < 2048; c += 256) {
                    int code = c & 127, k8l = c >> 7;
                    cp16(sb + BS_OFF + nb * 32768 + (k8l * 128 + code) * 16,
                         g_ch + ((size_t)(nt * NTT + code) * DDIM +
                                 (nkc * 16 + k8l) * 8));
                }
                cp_commit();
            }
            if (kc == 0) {
#pragma unroll
                for (int i = 0; i < 7; i++)
#pragma unroll
                    for (int j = 0; j < 8; j++)
                        acc[i][j] = __half2half2(__ushort_as_half(0));
            }

            const uint32_t aoff = AS_OFF + kc * 16 * (MT * 16);
            const uint32_t boff = BS_OFF + buf * 32768;
#pragma unroll 2
            for (int k8 = 0; k8 < 16; k8++) {
                uint4 av[7], bv[8];
#pragma unroll
                for (int i = 0; i < 7; i++)
                    av[i] = *(const uint4*)(smem + aoff +
                                            (k8 * MT + ty * 7 + i) * 16);
#pragma unroll
                for (int j = 0; j < 8; j++)
                    bv[j] = *(const uint4*)(smem + boff +
                                            (k8 * 128 + tx + 16 * j) * 16);
#pragma unroll
                for (int i = 0; i < 7; i++) {
                    const __half2* ah = (const __half2*)&av[i];
#pragma unroll
                    for (int j = 0; j < 8; j++) {
                        const __half2* bh = (const __half2*)&bv[j];
#pragma unroll
                        for (int p = 0; p < 4; p++)
                            acc[i][j] = __hfma2(ah[p], bh[p], acc[i][j]);
                    }
                }
            }
        }

        // ---- epilogue: v = cn - 2*(lo+hi); running row-min; collect ----
        float cnj[8];
#pragma unroll
        for (int j = 0; j < 8; j++)
            cnj[j] = cns[t * NTT + tx + 16 * j];   // smem broadcast, no LDG
#pragma unroll
        for (int i = 0; i < 7; i++) {
            int grow = row0 + ty * 7 + i;
            float v[8], vmin = 3.4e38f;
#pragma unroll
            for (int j = 0; j < 8; j++) {
                float2 f = __half22float2(acc[i][j]);
                v[j] = fmaf(-2.f, f.x + f.y, cnj[j]);
                vmin = fminf(vmin, v[j]);
            }
#pragma unroll
            for (int o = 8; o; o >>= 1)
                vmin = fminf(vmin, __shfl_xor_sync(0xffffffff, vmin, o));
            runmin[i] = fminf(runmin[i], vmin);
            if (grow < N_ROWS) {
                float thr = runmin[i] + MARGIN;
#pragma unroll
                for (int j = 0; j < 8; j++) {
                    if (v[j] <= thr) {
                        int pos = atomicAdd(&g_ccount[grow], 1);
                        if (pos < CAP)
                            g_cand[(size_t)grow * CAP + pos] =
                                t * NTT + tx + 16 * j;
                    }
                }
            }
        }
    }
}

// ---------------------------------------------------------------------------
// Kernel 3 (fused): exact fp32 rescore (reference rounding, lowest-index
// ties) + straight-through output + idx-float output + fp64 loss partials.
// One warp per row; x row stays in registers across all phases.
// ---------------------------------------------------------------------------
__global__ void __launch_bounds__(256)
rescore_gather_kernel(const float* __restrict__ x,
                      const float* __restrict__ cb,
                      float* __restrict__ out,
                      long long out_size) {
    __shared__ double wsum[8];
    const int wiw  = threadIdx.x >> 5;             // warp in block
    const int row  = blockIdx.x * 8 + wiw;
    const int lane = threadIdx.x & 31;

    float xr[16];
    const float* xp = x + (size_t)row * DDIM;
#pragma unroll
    for (int e = 0; e < 16; e++) xr[e] = xp[lane + e * 32];
    const float s = g_snorm[row];
    const int cnt = g_ccount[row];
    float bd = 3.4e38f;
    int   bi = K_CODES;

    if (cnt <= CAP) {
        for (int i = 0; i < cnt; i++) {
            int k = g_cand[(size_t)row * CAP + i];
            const float* cp = cb + (size_t)k * DDIM;
            float t = 0.f;
#pragma unroll
            for (int e = 0; e < 16; e++) t = fmaf(xr[e], cp[lane + e * 32], t);
#pragma unroll
            for (int o = 16; o; o >>= 1) t += __shfl_xor_sync(0xffffffff, t, o);
            float dist = (s - 2.0f * t) + g_cnorm[k];
            if (dist < bd || (dist == bd && k < bi)) { bd = dist; bi = k; }
        }
    } else {  // overflow fallback: exact full scan
        for (int k = 0; k < K_CODES; k++) {
            const float* cp = cb + (size_t)k * DDIM;
            float t = 0.f;
#pragma unroll
            for (int e = 0; e < 16; e++) t = fmaf(xr[e], cp[lane + e * 32], t);
#pragma unroll
            for (int o = 16; o; o >>= 1) t += __shfl_xor_sync(0xffffffff, t, o);
            float dist = (s - 2.0f * t) + g_cnorm[k];
            if (dist < bd) { bd = dist; bi = k; }
        }
    }
    // idx-float output (register-resident bi)
    const long long base = (long long)N_ROWS * DDIM;
    if (lane == 0 && out_size >= base + 2 + N_ROWS)
        out[base + 2 + row] = (float)bi;

    // ---- gather + straight-through output + loss (x row still in regs) ----
    const float* cp = cb + (size_t)bi * DDIM;
    float* op = out + (size_t)row * DDIM;
    double lsum = 0.0;
#pragma unroll
    for (int e = 0; e < 16; e++) {
        float zq = cp[lane + e * 32];
        float diff = zq - xr[e];
        op[lane + e * 32] = xr[e] + diff;          // reference rounding
        lsum += (double)diff * (double)diff;
    }
#pragma unroll
    for (int o = 16; o; o >>= 1)
        lsum += __shfl_xor_sync(0xffffffff, lsum, o);
    if (lane == 0) wsum[wiw] = lsum;
    __syncthreads();
    if (threadIdx.x == 0) {
        double b = 0.0;
#pragma unroll
        for (int w = 0; w < 8; w++) b += wsum[w];
        g_lpart[blockIdx.x] = b;
    }
}

// ---------------------------------------------------------------------------
// Kernel 4: deterministic loss reduction (single block) + loss writes.
// ---------------------------------------------------------------------------
__global__ void __launch_bounds__(256)
finalize_kernel(float* __restrict__ out, long long out_size) {
    __shared__ double part[256];
    const long long base = (long long)N_ROWS * DDIM;
    double s = 0.0;
#pragma unroll
    for (int i = 0; i < RG_BLOCKS / 256; i++)      // fixed order: deterministic
        s += g_lpart[threadIdx.x + i * 256];
    part[threadIdx.x] = s;
    __syncthreads();
    for (int r = 128; r; r >>= 1) {
        if (threadIdx.x < r) part[threadIdx.x] += part[threadIdx.x + r];
        __syncthreads();
    }
    if (threadIdx.x == 0 && out_size >= base + 2) {
        float loss = (float)(part[0] / ((double)N_ROWS * (double)DDIM));
        out[base]     = loss;
        out[base + 1] = loss;
    }
}

// ---------------------------------------------------------------------------
extern "C" void kernel_launch(void* const* d_in, const int* in_sizes, int n_in,
                              void* d_out, int out_size) {
    const float* x  = (const float*)d_in[0];
    const float* cb = (const float*)d_in[1];
    float* out = (float*)d_out;

    cudaFuncSetAttribute(vq_gemm_kernel,
                         cudaFuncAttributeMaxDynamicSharedMemorySize, SMEM_SZ);

    convert_kernel<<<(N_ROWS + K_CODES) / 8, 256>>>(x, cb);
    vq_gemm_kernel<<<NCTA, 256, SMEM_SZ>>>();
    rescore_gather_kernel<<<RG_BLOCKS, 256>>>(x, cb, out, (long long)out_size);
    finalize_kernel<<<1, 256>>>(out, (long long)out_size);
}

// round 16
// speedup vs baseline: 1.6588x; 1.6588x over previous
#include <cuda_runtime.h>
#include <cuda_fp16.h>
#include <cstdint>

#define N_ROWS  16384
#define DDIM    512
#define K_CODES 8192

#define MT 112                 // rows per CTA (147 CTAs = one wave on 148 SMs)
#define NCTA 147
#define NTT 128                // codes per tile
#define NTILES 64              // K_CODES / NTT
#define CAP 32
#define MARGIN 6.0e-4f
#define RG_BLOCKS 2048         // rescore/gather blocks (8 warps = 8 rows each)

// ---- scratch (__device__ globals; no cudaMalloc allowed) --------------------
__device__ float  g_snorm[N_ROWS];
__device__ float  g_cnorm[K_CODES];
__device__ int    g_idx[N_ROWS];
__device__ double g_lpart[RG_BLOCKS];
__device__ __half g_xh[(size_t)N_ROWS * DDIM];
__device__ __half g_ch[(size_t)K_CODES * DDIM];
__device__ int    g_ccount[N_ROWS];
__device__ int    g_cand[(size_t)N_ROWS * CAP];

// ---- dynamic smem ------------------------------------------------------------
#define AS_OFF 0               // 64 k8-blocks x 112 rows x 16B = 114688
#define BS_OFF 114688          // 2 bufs x (16 k8 x 128 codes x 16B) = 65536
#define SMEM_SZ 180224

static __device__ __forceinline__ uint32_t smem_u32(const void* p) {
    uint32_t a;
    asm("{ .reg .u64 t; cvta.to.shared.u64 t, %1; cvt.u32.u64 %0, t; }"
        : "=r"(a) : "l"(p));
    return a;
}
static __device__ __forceinline__ void cp16(uint32_t dst, const void* src) {
    asm volatile("cp.async.ca.shared.global [%0], [%1], 16;"
                 :: "r"(dst), "l"(src) : "memory");
}
static __device__ __forceinline__ void cp_commit() {
    asm volatile("cp.async.commit_group;" ::: "memory");
}
static __device__ __forceinline__ void cp_wait_all() {
    asm volatile("cp.async.wait_group 0;" ::: "memory");
}

// ---------------------------------------------------------------------------
// Kernel 1: fp16 convert + exact fp32 row norms; zero counters.
// One warp per row.
// ---------------------------------------------------------------------------
__global__ void convert_kernel(const float* __restrict__ x,
                               const float* __restrict__ cb) {
    int gtid = blockIdx.x * blockDim.x + threadIdx.x;
    if (gtid < N_ROWS) g_ccount[gtid] = 0;
    int warp = gtid >> 5;
    int lane = threadIdx.x & 31;
    if (warp >= N_ROWS + K_CODES) return;
    bool isx = warp < N_ROWS;
    int row = isx ? warp : warp - N_ROWS;
    const float4* base = (const float4*)((isx ? x : cb) + (size_t)row * DDIM);
    __half2* dst = (__half2*)((isx ? g_xh : g_ch) + (size_t)row * DDIM);

    float s = 0.f;
#pragma unroll
    for (int j = 0; j < 4; j++) {
        float4 v = base[lane + 32 * j];
        s += v.x * v.x + v.y * v.y + v.z * v.z + v.w * v.w;
        dst[(lane + 32 * j) * 2]     = __floats2half2_rn(v.x, v.y);
        dst[(lane + 32 * j) * 2 + 1] = __floats2half2_rn(v.z, v.w);
    }
#pragma unroll
    for (int o = 16; o; o >>= 1) s += __shfl_xor_sync(0xffffffff, s, o);
    if (lane == 0) {
        if (isx) g_snorm[row] = s;
        else     g_cnorm[row] = s;
    }
}

// ---------------------------------------------------------------------------
// Kernel 2: HFMA2 packed-fp16 filter GEMM (best-measured config, R13).
// 147 CTAs x 112 rows, one wave. 256 threads, thread tile 7x8, A resident,
// B double-buffered cp.async. Register running row-min + candidate collect.
// ---------------------------------------------------------------------------
__global__ void __launch_bounds__(256, 1)
vq_gemm_kernel() {
    extern __shared__ char smem[];
    const uint32_t sb = smem_u32(smem);
    const int tid = threadIdx.x;
    const int tx  = tid & 15;          // code lane: codes tx + 16*j
    const int ty  = tid >> 4;          // row group: rows ty*7 + i
    const int row0 = blockIdx.x * MT;

    // prologue: resident A (64 k8-blocks x 112 rows, clamped) + B chunk 0
    for (int c = tid; c < 64 * MT; c += 256) {
        int r = c % MT, k8 = c / MT;
        int gr = row0 + r; if (gr >= N_ROWS) gr = N_ROWS - 1;
        cp16(sb + AS_OFF + (k8 * MT + r) * 16,
             g_xh + ((size_t)gr * DDIM + k8 * 8));
    }
    for (int c = tid; c < 2048; c += 256) {
        int code = c & 127, k8l = c >> 7;
        cp16(sb + BS_OFF + (k8l * 128 + code) * 16,
             g_ch + ((size_t)code * DDIM + k8l * 8));
    }
    cp_commit();

    float runmin[7];
#pragma unroll
    for (int i = 0; i < 7; i++) runmin[i] = 3.4e38f;

    __half2 acc[7][8];

    for (int t = 0; t < NTILES; t++) {
        for (int kc = 0; kc < 4; kc++) {
            const int s = t * 4 + kc;
            const int buf = s & 1;
            cp_wait_all();
            __syncthreads();
            if (s + 1 < NTILES * 4) {     // prefetch next chunk
                const int nt = (s + 1) >> 2, nkc = (s + 1) & 3;
                const int nb = buf ^ 1;
                for (int c = tid; c < 2048; c += 256) {
                    int code = c & 127, k8l = c >> 7;
                    cp16(sb + BS_OFF + nb * 32768 + (k8l * 128 + code) * 16,
                         g_ch + ((size_t)(nt * NTT + code) * DDIM +
                                 (nkc * 16 + k8l) * 8));
                }
                cp_commit();
            }
            if (kc == 0) {
#pragma unroll
                for (int i = 0; i < 7; i++)
#pragma unroll
                    for (int j = 0; j < 8; j++)
                        acc[i][j] = __half2half2(__ushort_as_half(0));
            }

            const uint32_t aoff = AS_OFF + kc * 16 * (MT * 16);
            const uint32_t boff = BS_OFF + buf * 32768;
#pragma unroll 2
            for (int k8 = 0; k8 < 16; k8++) {
                uint4 av[7], bv[8];
#pragma unroll
                for (int i = 0; i < 7; i++)
                    av[i] = *(const uint4*)(smem + aoff +
                                            (k8 * MT + ty * 7 + i) * 16);
#pragma unroll
                for (int j = 0; j < 8; j++)
                    bv[j] = *(const uint4*)(smem + boff +
                                            (k8 * 128 + tx + 16 * j) * 16);
#pragma unroll
                for (int i = 0; i < 7; i++) {
                    const __half2* ah = (const __half2*)&av[i];
#pragma unroll
                    for (int j = 0; j < 8; j++) {
                        const __half2* bh = (const __half2*)&bv[j];
#pragma unroll
                        for (int p = 0; p < 4; p++)
                            acc[i][j] = __hfma2(ah[p], bh[p], acc[i][j]);
                    }
                }
            }
        }

        // ---- epilogue: v = cn - 2*(lo+hi); running row-min; collect ----
        float cnj[8];
#pragma unroll
        for (int j = 0; j < 8; j++)
            cnj[j] = __ldg(&g_cnorm[t * NTT + tx + 16 * j]);
#pragma unroll
        for (int i = 0; i < 7; i++) {
            int grow = row0 + ty * 7 + i;
            float v[8], vmin = 3.4e38f;
#pragma unroll
            for (int j = 0; j < 8; j++) {
                float2 f = __half22float2(acc[i][j]);
                v[j] = fmaf(-2.f, f.x + f.y, cnj[j]);
                vmin = fminf(vmin, v[j]);
            }
#pragma unroll
            for (int o = 8; o; o >>= 1)
                vmin = fminf(vmin, __shfl_xor_sync(0xffffffff, vmin, o));
            runmin[i] = fminf(runmin[i], vmin);
            if (grow < N_ROWS) {
                float thr = runmin[i] + MARGIN;
#pragma unroll
                for (int j = 0; j < 8; j++) {
                    if (v[j] <= thr) {
                        int pos = atomicAdd(&g_ccount[grow], 1);
                        if (pos < CAP)
                            g_cand[(size_t)grow * CAP + pos] =
                                t * NTT + tx + 16 * j;
                    }
                }
            }
        }
    }
}

// ---------------------------------------------------------------------------
// Kernel 3 (fused): exact fp32 rescore (reference rounding, lowest-index
// ties) + straight-through output write + fp64 loss partials.
// One warp per row; x row stays in registers across both phases.
// ---------------------------------------------------------------------------
__global__ void __launch_bounds__(256)
rescore_gather_kernel(const float* __restrict__ x,
                      const float* __restrict__ cb,
                      float* __restrict__ out) {
    __shared__ double wsum[8];
    const int wiw  = threadIdx.x >> 5;             // warp in block
    const int row  = blockIdx.x * 8 + wiw;
    const int lane = threadIdx.x & 31;

    float xr[16];
    const float* xp = x + (size_t)row * DDIM;
#pragma unroll
    for (int e = 0; e < 16; e++) xr[e] = xp[lane + e * 32];
    const float s = g_snorm[row];
    const int cnt = g_ccount[row];
    float bd = 3.4e38f;
    int   bi = K_CODES;

    if (cnt <= CAP) {
        for (int i = 0; i < cnt; i++) {
            int k = g_cand[(size_t)row * CAP + i];
            const float* cp = cb + (size_t)k * DDIM;
            float t = 0.f;
#pragma unroll
            for (int e = 0; e < 16; e++) t = fmaf(xr[e], cp[lane + e * 32], t);
#pragma unroll
            for (int o = 16; o; o >>= 1) t += __shfl_xor_sync(0xffffffff, t, o);
            float dist = (s - 2.0f * t) + g_cnorm[k];
            if (dist < bd || (dist == bd && k < bi)) { bd = dist; bi = k; }
        }
    } else {  // overflow fallback: exact full scan
        for (int k = 0; k < K_CODES; k++) {
            const float* cp = cb + (size_t)k * DDIM;
            float t = 0.f;
#pragma unroll
            for (int e = 0; e < 16; e++) t = fmaf(xr[e], cp[lane + e * 32], t);
#pragma unroll
            for (int o = 16; o; o >>= 1) t += __shfl_xor_sync(0xffffffff, t, o);
            float dist = (s - 2.0f * t) + g_cnorm[k];
            if (dist < bd) { bd = dist; bi = k; }
        }
    }
    if (lane == 0) g_idx[row] = bi;

    // ---- gather + straight-through output + loss (x row still in regs) ----
    const float* cp = cb + (size_t)bi * DDIM;
    float* op = out + (size_t)row * DDIM;
    double lsum = 0.0;
#pragma unroll
    for (int e = 0; e < 16; e++) {
        float zq = cp[lane + e * 32];
        float diff = zq - xr[e];
        op[lane + e * 32] = xr[e] + diff;          // reference rounding
        lsum += (double)diff * (double)diff;
    }
#pragma unroll
    for (int o = 16; o; o >>= 1)
        lsum += __shfl_xor_sync(0xffffffff, lsum, o);
    if (lane == 0) wsum[wiw] = lsum;
    __syncthreads();
    if (threadIdx.x == 0) {
        double b = 0.0;
#pragma unroll
        for (int w = 0; w < 8; w++) b += wsum[w];
        g_lpart[blockIdx.x] = b;
    }
}

// ---------------------------------------------------------------------------
// Kernel 4: deterministic loss reduction + losses + indices.
// ---------------------------------------------------------------------------
__global__ void __launch_bounds__(256)
finalize_kernel(float* __restrict__ out, long long out_size) {
    __shared__ double part[256];
    const long long base = (long long)N_ROWS * DDIM;
    if (blockIdx.x == 0) {
        double s = 0.0;
#pragma unroll
        for (int i = 0; i < RG_BLOCKS / 256; i++)      // fixed order: deterministic
            s += g_lpart[threadIdx.x + i * 256];
        part[threadIdx.x] = s;
        __syncthreads();
        for (int r = 128; r; r >>= 1) {
            if (threadIdx.x < r) part[threadIdx.x] += part[threadIdx.x + r];
            __syncthreads();
        }
        if (threadIdx.x == 0 && out_size >= base + 2) {
            float loss = (float)(part[0] / ((double)N_ROWS * (double)DDIM));
            out[base]     = loss;
            out[base + 1] = loss;
        }
    }
    if (out_size >= base + 2 + N_ROWS) {
        for (int n = blockIdx.x * blockDim.x + threadIdx.x; n < N_ROWS;
             n += gridDim.x * blockDim.x)
            out[base + 2 + n] = (float)g_idx[n];
    }
}

// ---------------------------------------------------------------------------
extern "C" void kernel_launch(void* const* d_in, const int* in_sizes, int n_in,
                              void* d_out, int out_size) {
    const float* x  = (const float*)d_in[0];
    const float* cb = (const float*)d_in[1];
    float* out = (float*)d_out;

    cudaFuncSetAttribute(vq_gemm_kernel,
                         cudaFuncAttributeMaxDynamicSharedMemorySize, SMEM_SZ);

    convert_kernel<<<(N_ROWS + K_CODES) / 8, 256>>>(x, cb);
    vq_gemm_kernel<<<NCTA, 256, SMEM_SZ>>>();
    rescore_gather_kernel<<<RG_BLOCKS, 256>>>(x, cb, out);
    finalize_kernel<<<64, 256>>>(out, (long long)out_size);
}

// round 17
// speedup vs baseline: 1.6709x; 1.0073x over previous
#include <cuda_runtime.h>
#include <cuda_fp16.h>
#include <cstdint>

#define N_ROWS  16384
#define DDIM    512
#define K_CODES 8192

#define MT 112                 // rows per CTA (147 CTAs = one wave on 148 SMs)
#define NCTA 147
#define NTT 128                // codes per tile
#define NTILES 64              // K_CODES / NTT
#define CAP 32
#define MARGIN 6.0e-4f
#define RG_BLOCKS 2048         // rescore/gather blocks (8 warps = 8 rows each)

// ---- scratch (__device__ globals; no cudaMalloc allowed) --------------------
__device__ float  g_snorm[N_ROWS];
__device__ float  g_cnorm[K_CODES];
__device__ int    g_idx[N_ROWS];
__device__ double g_lpart[RG_BLOCKS];
__device__ __half g_xh[(size_t)N_ROWS * DDIM];
__device__ __half g_ch[(size_t)K_CODES * DDIM];
__device__ int    g_ccount[N_ROWS];
__device__ int    g_cand[(size_t)N_ROWS * CAP];

// ---- dynamic smem ------------------------------------------------------------
#define AS_OFF 0               // 64 k8-blocks x 112 rows x 16B = 114688
#define BS_OFF 114688          // 2 bufs x (16 k8 x 128 codes x 16B) = 65536
#define SMEM_SZ 180224

static __device__ __forceinline__ uint32_t smem_u32(const void* p) {
    uint32_t a;
    asm("{ .reg .u64 t; cvta.to.shared.u64 t, %1; cvt.u32.u64 %0, t; }"
        : "=r"(a) : "l"(p));
    return a;
}
// L2-only (L1-bypass) 16B async copy: streaming operands with zero L1 reuse.
static __device__ __forceinline__ void cp16(uint32_t dst, const void* src) {
    asm volatile("cp.async.cg.shared.global [%0], [%1], 16;"
                 :: "r"(dst), "l"(src) : "memory");
}
static __device__ __forceinline__ void cp_commit() {
    asm volatile("cp.async.commit_group;" ::: "memory");
}
static __device__ __forceinline__ void cp_wait_all() {
    asm volatile("cp.async.wait_group 0;" ::: "memory");
}

// ---------------------------------------------------------------------------
// Kernel 1: fp16 convert + exact fp32 row norms; zero counters.
// One warp per row.
// ---------------------------------------------------------------------------
__global__ void convert_kernel(const float* __restrict__ x,
                               const float* __restrict__ cb) {
    int gtid = blockIdx.x * blockDim.x + threadIdx.x;
    if (gtid < N_ROWS) g_ccount[gtid] = 0;
    int warp = gtid >> 5;
    int lane = threadIdx.x & 31;
    if (warp >= N_ROWS + K_CODES) return;
    bool isx = warp < N_ROWS;
    int row = isx ? warp : warp - N_ROWS;
    const float4* base = (const float4*)((isx ? x : cb) + (size_t)row * DDIM);
    __half2* dst = (__half2*)((isx ? g_xh : g_ch) + (size_t)row * DDIM);

    float s = 0.f;
#pragma unroll
    for (int j = 0; j < 4; j++) {
        float4 v = base[lane + 32 * j];
        s += v.x * v.x + v.y * v.y + v.z * v.z + v.w * v.w;
        dst[(lane + 32 * j) * 2]     = __floats2half2_rn(v.x, v.y);
        dst[(lane + 32 * j) * 2 + 1] = __floats2half2_rn(v.z, v.w);
    }
#pragma unroll
    for (int o = 16; o; o >>= 1) s += __shfl_xor_sync(0xffffffff, s, o);
    if (lane == 0) {
        if (isx) g_snorm[row] = s;
        else     g_cnorm[row] = s;
    }
}

// ---------------------------------------------------------------------------
// Kernel 2: HFMA2 packed-fp16 filter GEMM (best-measured config; cp.async
// now L1-bypassing). 147 CTAs x 112 rows, one wave. 256 threads, thread
// tile 7x8, A resident, B double-buffered. Row-min + candidate collect.
// ---------------------------------------------------------------------------
__global__ void __launch_bounds__(256, 1)
vq_gemm_kernel() {
    extern __shared__ char smem[];
    const uint32_t sb = smem_u32(smem);
    const int tid = threadIdx.x;
    const int tx  = tid & 15;          // code lane: codes tx + 16*j
    const int ty  = tid >> 4;          // row group: rows ty*7 + i
    const int row0 = blockIdx.x * MT;

    // prologue: resident A (64 k8-blocks x 112 rows, clamped) + B chunk 0
    for (int c = tid; c < 64 * MT; c += 256) {
        int r = c % MT, k8 = c / MT;
        int gr = row0 + r; if (gr >= N_ROWS) gr = N_ROWS - 1;
        cp16(sb + AS_OFF + (k8 * MT + r) * 16,
             g_xh + ((size_t)gr * DDIM + k8 * 8));
    }
    for (int c = tid; c < 2048; c += 256) {
        int code = c & 127, k8l = c >> 7;
        cp16(sb + BS_OFF + (k8l * 128 + code) * 16,
             g_ch + ((size_t)code * DDIM + k8l * 8));
    }
    cp_commit();

    float runmin[7];
#pragma unroll
    for (int i = 0; i < 7; i++) runmin[i] = 3.4e38f;

    __half2 acc[7][8];

    for (int t = 0; t < NTILES; t++) {
        for (int kc = 0; kc < 4; kc++) {
            const int s = t * 4 + kc;
            const int buf = s & 1;
            cp_wait_all();
            __syncthreads();
            if (s + 1 < NTILES * 4) {     // prefetch next chunk
                const int nt = (s + 1) >> 2, nkc = (s + 1) & 3;
                const int nb = buf ^ 1;
                for (int c = tid; c < 2048; c += 256) {
                    int code = c & 127, k8l = c >> 7;
                    cp16(sb + BS_OFF + nb * 32768 + (k8l * 128 + code) * 16,
                         g_ch + ((size_t)(nt * NTT + code) * DDIM +
                                 (nkc * 16 + k8l) * 8));
                }
                cp_commit();
            }
            if (kc == 0) {
#pragma unroll
                for (int i = 0; i < 7; i++)
#pragma unroll
                    for (int j = 0; j < 8; j++)
                        acc[i][j] = __half2half2(__ushort_as_half(0));
            }

            const uint32_t aoff = AS_OFF + kc * 16 * (MT * 16);
            const uint32_t boff = BS_OFF + buf * 32768;
#pragma unroll 2
            for (int k8 = 0; k8 < 16; k8++) {
                uint4 av[7], bv[8];
#pragma unroll
                for (int i = 0; i < 7; i++)
                    av[i] = *(const uint4*)(smem + aoff +
                                            (k8 * MT + ty * 7 + i) * 16);
#pragma unroll
                for (int j = 0; j < 8; j++)
                    bv[j] = *(const uint4*)(smem + boff +
                                            (k8 * 128 + tx + 16 * j) * 16);
#pragma unroll
                for (int i = 0; i < 7; i++) {
                    const __half2* ah = (const __half2*)&av[i];
#pragma unroll
                    for (int j = 0; j < 8; j++) {
                        const __half2* bh = (const __half2*)&bv[j];
#pragma unroll
                        for (int p = 0; p < 4; p++)
                            acc[i][j] = __hfma2(ah[p], bh[p], acc[i][j]);
                    }
                }
            }
        }

        // ---- epilogue: v = cn - 2*(lo+hi); running row-min; collect ----
        float cnj[8];
#pragma unroll
        for (int j = 0; j < 8; j++)
            cnj[j] = __ldg(&g_cnorm[t * NTT + tx + 16 * j]);
#pragma unroll
        for (int i = 0; i < 7; i++) {
            int grow = row0 + ty * 7 + i;
            float v[8], vmin = 3.4e38f;
#pragma unroll
            for (int j = 0; j < 8; j++) {
                float2 f = __half22float2(acc[i][j]);
                v[j] = fmaf(-2.f, f.x + f.y, cnj[j]);
                vmin = fminf(vmin, v[j]);
            }
#pragma unroll
            for (int o = 8; o; o >>= 1)
                vmin = fminf(vmin, __shfl_xor_sync(0xffffffff, vmin, o));
            runmin[i] = fminf(runmin[i], vmin);
            if (grow < N_ROWS) {
                float thr = runmin[i] + MARGIN;
#pragma unroll
                for (int j = 0; j < 8; j++) {
                    if (v[j] <= thr) {
                        int pos = atomicAdd(&g_ccount[grow], 1);
                        if (pos < CAP)
                            g_cand[(size_t)grow * CAP + pos] =
                                t * NTT + tx + 16 * j;
                    }
                }
            }
        }
    }
}

// ---------------------------------------------------------------------------
// Kernel 3 (fused): exact fp32 rescore (reference rounding, lowest-index
// ties) + straight-through output write + fp64 loss partials.
// One warp per row; x row stays in registers across both phases.
// ---------------------------------------------------------------------------
__global__ void __launch_bounds__(256)
rescore_gather_kernel(const float* __restrict__ x,
                      const float* __restrict__ cb,
                      float* __restrict__ out) {
    __shared__ double wsum[8];
    const int wiw  = threadIdx.x >> 5;             // warp in block
    const int row  = blockIdx.x * 8 + wiw;
    const int lane = threadIdx.x & 31;

    float xr[16];
    const float* xp = x + (size_t)row * DDIM;
#pragma unroll
    for (int e = 0; e < 16; e++) xr[e] = xp[lane + e * 32];
    const float s = g_snorm[row];
    const int cnt = g_ccount[row];
    float bd = 3.4e38f;
    int   bi = K_CODES;

    if (cnt <= CAP) {
        for (int i = 0; i < cnt; i++) {
            int k = g_cand[(size_t)row * CAP + i];
            const float* cp = cb + (size_t)k * DDIM;
            float t = 0.f;
#pragma unroll
            for (int e = 0; e < 16; e++) t = fmaf(xr[e], cp[lane + e * 32], t);
#pragma unroll
            for (int o = 16; o; o >>= 1) t += __shfl_xor_sync(0xffffffff, t, o);
            float dist = (s - 2.0f * t) + g_cnorm[k];
            if (dist < bd || (dist == bd && k < bi)) { bd = dist; bi = k; }
        }
    } else {  // overflow fallback: exact full scan
        for (int k = 0; k < K_CODES; k++) {
            const float* cp = cb + (size_t)k * DDIM;
            float t = 0.f;
#pragma unroll
            for (int e = 0; e < 16; e++) t = fmaf(xr[e], cp[lane + e * 32], t);
#pragma unroll
            for (int o = 16; o; o >>= 1) t += __shfl_xor_sync(0xffffffff, t, o);
            float dist = (s - 2.0f * t) + g_cnorm[k];
            if (dist < bd) { bd = dist; bi = k; }
        }
    }
    if (lane == 0) g_idx[row] = bi;

    // ---- gather + straight-through output + loss (x row still in regs) ----
    const float* cp = cb + (size_t)bi * DDIM;
    float* op = out + (size_t)row * DDIM;
    double lsum = 0.0;
#pragma unroll
    for (int e = 0; e < 16; e++) {
        float zq = cp[lane + e * 32];
        float diff = zq - xr[e];
        op[lane + e * 32] = xr[e] + diff;          // reference rounding
        lsum += (double)diff * (double)diff;
    }
#pragma unroll
    for (int o = 16; o; o >>= 1)
        lsum += __shfl_xor_sync(0xffffffff, lsum, o);
    if (lane == 0) wsum[wiw] = lsum;
    __syncthreads();
    if (threadIdx.x == 0) {
        double b = 0.0;
#pragma unroll
        for (int w = 0; w < 8; w++) b += wsum[w];
        g_lpart[blockIdx.x] = b;
    }
}

// ---------------------------------------------------------------------------
// Kernel 4: deterministic loss reduction + losses + indices.
// ---------------------------------------------------------------------------
__global__ void __launch_bounds__(256)
finalize_kernel(float* __restrict__ out, long long out_size) {
    __shared__ double part[256];
    const long long base = (long long)N_ROWS * DDIM;
    if (blockIdx.x == 0) {
        double s = 0.0;
#pragma unroll
        for (int i = 0; i < RG_BLOCKS / 256; i++)      // fixed order: deterministic
            s += g_lpart[threadIdx.x + i * 256];
        part[threadIdx.x] = s;
        __syncthreads();
        for (int r = 128; r; r >>= 1) {
            if (threadIdx.x < r) part[threadIdx.x] += part[threadIdx.x + r];
            __syncthreads();
        }
        if (threadIdx.x == 0 && out_size >= base + 2) {
            float loss = (float)(part[0] / ((double)N_ROWS * (double)DDIM));
            out[base]     = loss;
            out[base + 1] = loss;
        }
    }
    if (out_size >= base + 2 + N_ROWS) {
        for (int n = blockIdx.x * blockDim.x + threadIdx.x; n < N_ROWS;
             n += gridDim.x * blockDim.x)
            out[base + 2 + n] = (float)g_idx[n];
    }
}

// ---------------------------------------------------------------------------
extern "C" void kernel_launch(void* const* d_in, const int* in_sizes, int n_in,
                              void* d_out, int out_size) {
    const float* x  = (const float*)d_in[0];
    const float* cb = (const float*)d_in[1];
    float* out = (float*)d_out;

    cudaFuncSetAttribute(vq_gemm_kernel,
                         cudaFuncAttributeMaxDynamicSharedMemorySize, SMEM_SZ);

    convert_kernel<<<(N_ROWS + K_CODES) / 8, 256>>>(x, cb);
    vq_gemm_kernel<<<NCTA, 256, SMEM_SZ>>>();
    rescore_gather_kernel<<<RG_BLOCKS, 256>>>(x, cb, out);
    finalize_kernel<<<64, 256>>>(out, (long long)out_size);
}